// round 10
// baseline (speedup 1.0000x reference)
#include <cuda_runtime.h>
#include <cuda_fp16.h>
#include <math.h>
#include <stdint.h>

// ---------------------------------------------------------------------------
// Problem constants
// ---------------------------------------------------------------------------
constexpr int TT     = 256;    // ids_len
constexpr int HH     = 2048;   // hidden
constexpr int FF     = 8192;   // mlp intermediate
constexpr int VV     = 32000;  // vocab
constexpr int HDIM   = 128;
constexpr int NHEAD  = 16;
constexpr int KVHEAD = 4;
constexpr int HISTL  = 1024;
constexpr int KVLEN  = 1280;   // HIST + T
constexpr int LAYERS = 4;
constexpr float SCALE = 0.29730177875068026f; // 128^-0.25

constexpr long NK_LAYER = (long)KVHEAD * HDIM * KVLEN;   // 655360
constexpr long NV_OFF   = (long)LAYERS * NK_LAYER;       // 2621440
constexpr long TOK_OFF  = 2 * NV_OFF;                    // 5242880

// ---------------------------------------------------------------------------
// Static device scratch (no allocations allowed)
// ---------------------------------------------------------------------------
__device__ float g_h[TT * HH];
__device__ float g_hn[TT * HH];
__device__ float g_q[TT * HH];
__device__ float g_scores[NHEAD * TT * KVLEN];
__device__ float g_attnout[TT * HH];
__device__ float g_gate[TT * FF];
__device__ float g_part[8 * TT * HH];   // split-K partials (max 8 x 256x2048)
__device__ float g_cos[TT * 64];
__device__ float g_sin[TT * 64];
__device__ float g_logits[VV];
__device__ int   g_eq_dtype;   // 0=uint8 packed, 1=int32, 2=float32

// ---------------------------------------------------------------------------
// Dtype sniffer (embed_q may arrive as uint8 / int32 / float32)
// ---------------------------------------------------------------------------
__global__ void sniff_k(const int* __restrict__ eq_words) {
    __shared__ int not_int, not_flt;
    if (threadIdx.x == 0) { not_int = 0; not_flt = 0; }
    __syncthreads();
    for (int i = threadIdx.x; i < 4096; i += 256) {
        int x = eq_words[i];
        if (!(x >= 0 && x < 256)) not_int = 1;
        float f = __int_as_float(x);
        if (!(f >= 0.f && f < 256.f && f == rintf(f))) not_flt = 1;
    }
    __syncthreads();
    if (threadIdx.x == 0)
        g_eq_dtype = (!not_int) ? 1 : ((!not_flt) ? 2 : 0);
}

// ---------------------------------------------------------------------------
// FP16 tensor-core GEMM, double-buffered smem.  C[M,N] = A[M,K] @ B[K,N]
//  - batch via blockIdx.z (A += z*sA, B += (z/bdiv)*sB, C += z*sC), OR
//  - split-K via blockIdx.z (slice K, write C + z*partElems, ldc=N)
//  - emode 2: C[i] = silu(peer[i]) * acc   (SwiGLU fusion)
// ---------------------------------------------------------------------------
__device__ __forceinline__ void ldsm_x4(uint32_t& r0, uint32_t& r1,
                                        uint32_t& r2, uint32_t& r3, uint32_t a) {
    asm volatile("ldmatrix.sync.aligned.m8n8.x4.shared.b16 {%0,%1,%2,%3}, [%4];"
                 : "=r"(r0), "=r"(r1), "=r"(r2), "=r"(r3) : "r"(a));
}
__device__ __forceinline__ void ldsm_x4t(uint32_t& r0, uint32_t& r1,
                                         uint32_t& r2, uint32_t& r3, uint32_t a) {
    asm volatile("ldmatrix.sync.aligned.m8n8.x4.trans.shared.b16 {%0,%1,%2,%3}, [%4];"
                 : "=r"(r0), "=r"(r1), "=r"(r2), "=r"(r3) : "r"(a));
}
__device__ __forceinline__ void mma_f16(float* c, const uint32_t* a, const uint32_t* b) {
    asm volatile(
        "mma.sync.aligned.m16n8k16.row.col.f32.f16.f16.f32 "
        "{%0,%1,%2,%3}, {%4,%5,%6,%7}, {%8,%9}, {%0,%1,%2,%3};"
        : "+f"(c[0]), "+f"(c[1]), "+f"(c[2]), "+f"(c[3])
        : "r"(a[0]), "r"(a[1]), "r"(a[2]), "r"(a[3]), "r"(b[0]), "r"(b[1]));
}
__device__ __forceinline__ uint2 pack4(float4 v) {
    __half2 h0 = __floats2half2_rn(v.x, v.y);
    __half2 h1 = __floats2half2_rn(v.z, v.w);
    return make_uint2(*reinterpret_cast<uint32_t*>(&h0),
                      *reinterpret_cast<uint32_t*>(&h1));
}
__device__ __forceinline__ float silu_f(float g) { return g / (1.0f + expf(-g)); }

template <int BM, int BN, int WM, int WN, int NTH>
__global__ void __launch_bounds__(NTH)
gemm_f16(const float* __restrict__ A, const float* __restrict__ B,
         float* __restrict__ C,
         int M, int N, int K, int lda, int ldb, int ldc,
         long sA, long sB, long sC, int bdiv, int splitK, long partElems,
         int emode, const float* __restrict__ peer) {
    constexpr int BK   = 32;
    constexpr int WGN  = BN / WN;
    constexpr int MT   = WM / 16;
    constexpr int NT   = WN / 8;
    constexpr int AP   = BM * (BK / 4) / NTH;
    constexpr int BP   = BK * (BN / 4) / NTH;
    constexpr int ASTR = BK + 8;   // halves; 80B rows -> conflict-free ldmatrix
    constexpr int BSTR = BN + 8;

    __shared__ __half As[2][BM][ASTR];
    __shared__ __half Bs[2][BK][BSTR];

    const int z = blockIdx.z;
    int kbeg, kend;
    if (splitK > 1) {
        C += (long)z * partElems;
        const int Kb = K / splitK;
        kbeg = z * Kb;
        kend = kbeg + Kb;
    } else {
        A += (long)z * sA;
        B += (long)(z / bdiv) * sB;
        C += (long)z * sC;
        kbeg = 0;
        kend = K;
    }

    const int tid  = threadIdx.x;
    const int wid  = tid >> 5;
    const int lane = tid & 31;
    const int grp  = lane >> 2;
    const int t4   = lane & 3;
    const int wm0  = (wid / WGN) * WM;
    const int wn0  = (wid % WGN) * WN;
    const int bm   = blockIdx.y * BM;
    const int bn   = blockIdx.x * BN;

    const int lrow = lane & 15;
    const int lcol = (lane & 16) ? 8 : 0;

    float acc[MT][NT][4];
#pragma unroll
    for (int i = 0; i < MT; i++)
#pragma unroll
        for (int j = 0; j < NT; j++)
#pragma unroll
            for (int r = 0; r < 4; r++) acc[i][j][r] = 0.f;

    uint2 ra[AP], rb[BP];
    const int niter = (kend - kbeg) / BK;

    // ---- prologue: tile 0 -> regs -> stage 0 ----
#pragma unroll
    for (int p = 0; p < AP; p++) {
        int f = p * NTH + tid;
        int row = f >> 3, kq = f & 7;
        ra[p] = pack4(*(const float4*)(A + (long)(bm + row) * lda + (kbeg + kq * 4)));
    }
#pragma unroll
    for (int p = 0; p < BP; p++) {
        int f = p * NTH + tid;
        int row = f / (BN / 4), c4 = f % (BN / 4);
        rb[p] = pack4(*(const float4*)(B + (long)(kbeg + row) * ldb + (bn + c4 * 4)));
    }
#pragma unroll
    for (int p = 0; p < AP; p++) {
        int f = p * NTH + tid;
        *(uint2*)&As[0][f >> 3][(f & 7) * 4] = ra[p];
    }
#pragma unroll
    for (int p = 0; p < BP; p++) {
        int f = p * NTH + tid;
        *(uint2*)&Bs[0][f / (BN / 4)][(f % (BN / 4)) * 4] = rb[p];
    }

    int cur = 0;
    for (int it = 0; it < niter; it++) {
        __syncthreads();   // stage 'cur' fully written; prior reads of 'cur^1' done
        if (it + 1 < niter) {
            const int k0g = kbeg + (it + 1) * BK;
#pragma unroll
            for (int p = 0; p < AP; p++) {
                int f = p * NTH + tid;
                int row = f >> 3, kq = f & 7;
                ra[p] = pack4(*(const float4*)(A + (long)(bm + row) * lda + (k0g + kq * 4)));
            }
#pragma unroll
            for (int p = 0; p < BP; p++) {
                int f = p * NTH + tid;
                int row = f / (BN / 4), c4 = f % (BN / 4);
                rb[p] = pack4(*(const float4*)(B + (long)(k0g + row) * ldb + (bn + c4 * 4)));
            }
        }
        const uint32_t asB = (uint32_t)__cvta_generic_to_shared(&As[cur][0][0]);
        const uint32_t bsB = (uint32_t)__cvta_generic_to_shared(&Bs[cur][0][0]);
#pragma unroll
        for (int ks = 0; ks < 2; ks++) {
            uint32_t af[MT][4];
#pragma unroll
            for (int mt = 0; mt < MT; mt++) {
                uint32_t ad = asB + 2u * ((wm0 + mt * 16 + lrow) * ASTR + ks * 16 + lcol);
                ldsm_x4(af[mt][0], af[mt][1], af[mt][2], af[mt][3], ad);
            }
            uint32_t bf[NT][2];
#pragma unroll
            for (int np = 0; np < NT / 2; np++) {
                uint32_t bd = bsB + 2u * ((ks * 16 + lrow) * BSTR + wn0 + np * 16 + lcol);
                ldsm_x4t(bf[2 * np][0], bf[2 * np][1],
                         bf[2 * np + 1][0], bf[2 * np + 1][1], bd);
            }
#pragma unroll
            for (int mt = 0; mt < MT; mt++)
#pragma unroll
                for (int nt = 0; nt < NT; nt++) mma_f16(acc[mt][nt], af[mt], bf[nt]);
        }
        if (it + 1 < niter) {
            const int nxt = cur ^ 1;
#pragma unroll
            for (int p = 0; p < AP; p++) {
                int f = p * NTH + tid;
                *(uint2*)&As[nxt][f >> 3][(f & 7) * 4] = ra[p];
            }
#pragma unroll
            for (int p = 0; p < BP; p++) {
                int f = p * NTH + tid;
                *(uint2*)&Bs[nxt][f / (BN / 4)][(f % (BN / 4)) * 4] = rb[p];
            }
            cur = nxt;
        }
    }

    // ---- epilogue ----
#pragma unroll
    for (int mt = 0; mt < MT; mt++) {
        const int r0 = bm + wm0 + mt * 16 + grp;
#pragma unroll
        for (int nt = 0; nt < NT; nt++) {
            const int c0 = bn + wn0 + nt * 8 + t4 * 2;
            long i00 = (long)r0 * ldc + c0;
            long i10 = (long)(r0 + 8) * ldc + c0;
            if (emode == 2) {
                C[i00]     = silu_f(peer[i00])     * acc[mt][nt][0];
                C[i00 + 1] = silu_f(peer[i00 + 1]) * acc[mt][nt][1];
                C[i10]     = silu_f(peer[i10])     * acc[mt][nt][2];
                C[i10 + 1] = silu_f(peer[i10 + 1]) * acc[mt][nt][3];
            } else {
                C[i00]     = acc[mt][nt][0];
                C[i00 + 1] = acc[mt][nt][1];
                C[i10]     = acc[mt][nt][2];
                C[i10 + 1] = acc[mt][nt][3];
            }
        }
    }
}

// ---------------------------------------------------------------------------
// Fused: h += sum_s part[s]  (residual into h), then hn = w * rms(h)
// One block per token row. Deterministic s-ascending order.
// ---------------------------------------------------------------------------
__global__ void res_norm_k(const float* __restrict__ part, int S, long stride,
                           float* __restrict__ h, const float* __restrict__ w,
                           float* __restrict__ hn) {
    int t = blockIdx.x;
    float4* hrow = (float4*)(h + (long)t * HH);
    __shared__ float red[256];
    float ssum = 0.f;
    for (int i = threadIdx.x; i < HH / 4; i += 256) {
        float4 a = hrow[i];
        for (int s = 0; s < S; s++) {
            float4 b = ((const float4*)(part + (long)s * stride + (long)t * HH))[i];
            a.x += b.x; a.y += b.y; a.z += b.z; a.w += b.w;
        }
        hrow[i] = a;
        ssum += a.x * a.x + a.y * a.y + a.z * a.z + a.w * a.w;
    }
    red[threadIdx.x] = ssum;
    __syncthreads();
    for (int o = 128; o > 0; o >>= 1) {
        if (threadIdx.x < o) red[threadIdx.x] += red[threadIdx.x + o];
        __syncthreads();
    }
    float inv = 1.0f / sqrtf(red[0] / (float)HH + 1e-6f);
    const float* hr = h + (long)t * HH;
    for (int d = threadIdx.x; d < HH; d += 256)
        hn[(long)t * HH + d] = w[d] * hr[d] * inv;
}

// ---------------------------------------------------------------------------
// Elementwise / norm / attention helper kernels
// ---------------------------------------------------------------------------
__global__ void rope_table_k() {
    int i = blockIdx.x * blockDim.x + threadIdx.x;
    if (i >= TT * 64) return;
    int t = i / 64, j = i % 64;
    float freq = powf(10000.0f, -((float)(2 * j)) / 128.0f);
    float ang = (float)(HISTL + t) * freq;
    g_cos[i] = __half2float(__float2half(cosf(ang)));
    g_sin[i] = __half2float(__float2half(sinf(ang)));
}

__global__ void embed_k(const int* __restrict__ ids, const void* __restrict__ eq,
                        const float* __restrict__ esc, const float* __restrict__ ezp) {
    int t = blockIdx.x;
    int id = ids[t];
    float sc = esc[id], zp = ezp[id];
    int dt = g_eq_dtype;
    long off = (long)id * HH;
    for (int d = threadIdx.x; d < HH; d += blockDim.x) {
        float qv;
        if (dt == 1)      qv = (float)((const int*)eq)[off + d];
        else if (dt == 2) qv = ((const float*)eq)[off + d];
        else              qv = (float)((const unsigned char*)eq)[off + d];
        g_h[t * HH + d] = qv * sc + zp;
    }
}

__global__ void rmsnorm_k(const float* __restrict__ x, const float* __restrict__ w,
                          float* __restrict__ y) {
    int t = blockIdx.x;
    const float* xr = x + (long)t * HH;
    __shared__ float red[256];
    float s = 0.f;
    for (int d = threadIdx.x; d < HH; d += 256) {
        float v = xr[d];
        s += v * v;
    }
    red[threadIdx.x] = s;
    __syncthreads();
    for (int o = 128; o > 0; o >>= 1) {
        if (threadIdx.x < o) red[threadIdx.x] += red[threadIdx.x + o];
        __syncthreads();
    }
    float inv = 1.0f / sqrtf(red[0] / (float)HH + 1e-6f);
    for (int d = threadIdx.x; d < HH; d += 256) y[(long)t * HH + d] = w[d] * xr[d] * inv;
}

// split-K reduce (S=4) + RoPE + per-head RMS for Q -> g_q.  grid (T,NH), 128 thr
__global__ void rope_rms_q_k(const float* __restrict__ w, const float* __restrict__ part) {
    int t = blockIdx.x, h = blockIdx.y, d = threadIdx.x;
    long idx = (long)t * HH + h * HDIM + d;
    float x = part[idx] + part[idx + (long)TT * HH] +
              part[idx + 2L * TT * HH] + part[idx + 3L * TT * HH];
    __shared__ float sq[128];
    __shared__ float red[128];
    sq[d] = x;
    __syncthreads();
    float other = (d < 64) ? -sq[d + 64] : sq[d - 64];
    float c = g_cos[t * 64 + (d & 63)];
    float sn = g_sin[t * 64 + (d & 63)];
    float r = sq[d] * c + other * sn;
    red[d] = r * r;
    __syncthreads();
    for (int o = 64; o > 0; o >>= 1) {
        if (d < o) red[d] += red[d + o];
        __syncthreads();
    }
    float inv = 1.0f / sqrtf(red[0] / 128.0f + 1e-6f);
    g_q[idx] = (w[d] * SCALE) * r * inv;
}

// split-K reduce (S=4) + RoPE + per-head RMS for K -> nk[l][kvh][d][KV] col HIST+t
__global__ void rope_rms_k_k(const float* __restrict__ w, const float* __restrict__ part,
                             float* __restrict__ nk_l) {
    int t = blockIdx.x, h = blockIdx.y, d = threadIdx.x;
    long idx = (long)t * 512 + h * HDIM + d;
    float x = part[idx] + part[idx + (long)TT * 512] +
              part[idx + 2L * TT * 512] + part[idx + 3L * TT * 512];
    __shared__ float sq[128];
    __shared__ float red[128];
    sq[d] = x;
    __syncthreads();
    float other = (d < 64) ? -sq[d + 64] : sq[d - 64];
    float c = g_cos[t * 64 + (d & 63)];
    float sn = g_sin[t * 64 + (d & 63)];
    float r = sq[d] * c + other * sn;
    red[d] = r * r;
    __syncthreads();
    for (int o = 64; o > 0; o >>= 1) {
        if (d < o) red[d] += red[d + o];
        __syncthreads();
    }
    float inv = 1.0f / sqrtf(red[0] / 128.0f + 1e-6f);
    nk_l[(long)h * HDIM * KVLEN + (long)d * KVLEN + (HISTL + t)] = (w[d] * SCALE) * r * inv;
}

// split-K reduce (S=4) + store new V rows into nv[l]: [kvh][KV][HD]
__global__ void v_store_k(const float* __restrict__ part, float* __restrict__ nv_l) {
    int i = blockIdx.x * blockDim.x + threadIdx.x;
    if (i >= TT * 512) return;
    float v = part[i] + part[i + TT * 512] + part[i + 2 * TT * 512] + part[i + 3 * TT * 512];
    int t = i >> 9, r = i & 511;
    int kvh = r >> 7, d = r & 127;
    nv_l[(long)kvh * KVLEN * HDIM + (long)(HISTL + t) * HDIM + d] = v;
}

__global__ void copy_kcache_k(const float* __restrict__ kc, float* __restrict__ out) {
    long i = (long)blockIdx.x * blockDim.x + threadIdx.x;
    const long total4 = (long)LAYERS * KVHEAD * HDIM * HISTL / 4;
    if (i >= total4) return;
    long row = i >> 8;
    long c4 = i & 255;
    long lk = row >> 7;
    long d = row & 127;
    float4 v = ((const float4*)kc)[i];
    long dst = lk * ((long)HDIM * KVLEN) + d * KVLEN + c4 * 4;
    *(float4*)(out + dst) = v;
}

__global__ void copy_vcache_k(const float* __restrict__ vc, float* __restrict__ outv) {
    long i = (long)blockIdx.x * blockDim.x + threadIdx.x;
    const long per4 = (long)HISTL * HDIM / 4;
    const long total4 = (long)LAYERS * KVHEAD * per4;
    if (i >= total4) return;
    long lk = i / per4;
    long rem = i - lk * per4;
    float4 v = ((const float4*)vc)[i];
    long dst = lk * ((long)KVLEN * HDIM) + rem * 4;
    *(float4*)(outv + dst) = v;
}

__global__ void softmax_k(float* __restrict__ s, const float* __restrict__ flagp) {
    int t = blockIdx.x, h = blockIdx.y;
    float flag = flagp[0];
    float* row = s + ((long)h * TT + t) * KVLEN;
    __shared__ float red[256];
    float m = -1e30f;
    for (int c = threadIdx.x; c < KVLEN; c += 256) {
        float v = row[c] + ((c <= t) ? 0.f : -128.f * flag);
        m = fmaxf(m, v);
    }
    red[threadIdx.x] = m;
    __syncthreads();
    for (int o = 128; o > 0; o >>= 1) {
        if (threadIdx.x < o) red[threadIdx.x] = fmaxf(red[threadIdx.x], red[threadIdx.x + o]);
        __syncthreads();
    }
    float mx = red[0];
    __syncthreads();
    float sum = 0.f;
    for (int c = threadIdx.x; c < KVLEN; c += 256) {
        float v = row[c] + ((c <= t) ? 0.f : -128.f * flag);
        float e = expf(v - mx);
        row[c] = e;
        sum += e;
    }
    red[threadIdx.x] = sum;
    __syncthreads();
    for (int o = 128; o > 0; o >>= 1) {
        if (threadIdx.x < o) red[threadIdx.x] += red[threadIdx.x + o];
        __syncthreads();
    }
    float inv = 1.0f / red[0];
    for (int c = threadIdx.x; c < KVLEN; c += 256) row[c] *= inv;
}

// lm_head GEMV over the final normed row (hl)
__global__ void gemv_k(const float* __restrict__ W, const float* __restrict__ hl) {
    __shared__ float sh[HH];
    for (int i = threadIdx.x; i < HH; i += blockDim.x) sh[i] = hl[i];
    __syncthreads();
    int v = blockIdx.x * blockDim.x + threadIdx.x;
    if (v >= VV) return;
    float acc = 0.f;
#pragma unroll 8
    for (int h = 0; h < HH; h++) acc += sh[h] * __ldg(&W[(long)h * VV + v]);
    g_logits[v] = acc;
}

__global__ void argmax_k(float* __restrict__ out) {
    __shared__ float bv[256];
    __shared__ int bi[256];
    float best = -1e30f;
    int bidx = 0;
    for (int v = threadIdx.x; v < VV; v += 256) {
        float x = g_logits[v];
        if (x > best) { best = x; bidx = v; }
    }
    bv[threadIdx.x] = best;
    bi[threadIdx.x] = bidx;
    __syncthreads();
    for (int o = 128; o > 0; o >>= 1) {
        if (threadIdx.x < o) {
            float a = bv[threadIdx.x], b = bv[threadIdx.x + o];
            int ia = bi[threadIdx.x], ib = bi[threadIdx.x + o];
            if (b > a || (b == a && ib < ia)) { bv[threadIdx.x] = b; bi[threadIdx.x] = ib; }
        }
        __syncthreads();
    }
    if (threadIdx.x == 0) {
        out[TOK_OFF] = (float)bi[0];
        out[TOK_OFF + 1] = (float)KVLEN;
    }
}

// ---------------------------------------------------------------------------
// Host-side launch helpers
// ---------------------------------------------------------------------------
static void gemm_h128(const float* A, const float* B, float* C, int M, int N, int K,
                      int lda, int ldb, int ldc, long sA, long sB, long sC,
                      int bdiv, int batch, int splitK, long partElems,
                      int emode = 0, const float* peer = nullptr) {
    dim3 g(N / 128, M / 128, splitK > 1 ? splitK : batch);
    gemm_f16<128, 128, 64, 32, 256><<<g, 256>>>(A, B, C, M, N, K, lda, ldb, ldc,
                                                sA, sB, sC, bdiv, splitK, partElems,
                                                emode, peer);
}
static void gemm_h64(const float* A, const float* B, float* C, int M, int N, int K,
                     int lda, int ldb, int ldc, long sA, long sB, long sC,
                     int bdiv, int batch, int splitK, long partElems) {
    dim3 g(N / 64, M / 64, splitK > 1 ? splitK : batch);
    gemm_f16<64, 64, 32, 32, 128><<<g, 128>>>(A, B, C, M, N, K, lda, ldb, ldc,
                                              sA, sB, sC, bdiv, splitK, partElems,
                                              0, nullptr);
}

extern "C" void kernel_launch(void* const* d_in, const int* in_sizes, int n_in,
                              void* d_out, int out_size) {
    const int* ids      = (const int*)d_in[0];
    const float* kcache = (const float*)d_in[1];
    const float* vcache = (const float*)d_in[2];
    const float* flag   = (const float*)d_in[3];

    int base = 6;
    for (int i = 4; i <= 6 && i < n_in; i++) {
        if (in_sizes[i] == VV * HH) { base = i; break; }
    }
    const void* eq          = d_in[base + 0];
    const float* esc        = (const float*)d_in[base + 1];
    const float* ezp        = (const float*)d_in[base + 2];
    const float* in_ln      = (const float*)d_in[base + 3];
    const float* wq         = (const float*)d_in[base + 4];
    const float* wk         = (const float*)d_in[base + 5];
    const float* wv         = (const float*)d_in[base + 6];
    const float* wo         = (const float*)d_in[base + 7];
    const float* q_ln       = (const float*)d_in[base + 8];
    const float* k_ln       = (const float*)d_in[base + 9];
    const float* post_ln    = (const float*)d_in[base + 10];
    const float* w_gate     = (const float*)d_in[base + 11];
    const float* w_up       = (const float*)d_in[base + 12];
    const float* w_down     = (const float*)d_in[base + 13];
    const float* final_w    = (const float*)d_in[base + 14];
    const float* lm_head    = (const float*)d_in[base + 15];
    float* out = (float*)d_out;

    float *p_h, *p_hn, *p_q, *p_sc, *p_ao, *p_ga, *p_part;
    cudaGetSymbolAddress((void**)&p_h, g_h);
    cudaGetSymbolAddress((void**)&p_hn, g_hn);
    cudaGetSymbolAddress((void**)&p_q, g_q);
    cudaGetSymbolAddress((void**)&p_sc, g_scores);
    cudaGetSymbolAddress((void**)&p_ao, g_attnout);
    cudaGetSymbolAddress((void**)&p_ga, g_gate);
    cudaGetSymbolAddress((void**)&p_part, g_part);

    sniff_k<<<1, 256>>>((const int*)eq);
    rope_table_k<<<64, 256>>>();
    copy_kcache_k<<<2048, 256>>>(kcache, out);
    copy_vcache_k<<<2048, 256>>>(vcache, out + NV_OFF);
    embed_k<<<256, 256>>>(ids, eq, esc, ezp);

    // first layer input norm
    rmsnorm_k<<<TT, 256>>>(p_h, in_ln, p_hn);

    for (int l = 0; l < LAYERS; l++) {
        float* nk_l = out + (long)l * NK_LAYER;
        float* nv_l = out + NV_OFF + (long)l * NK_LAYER;

        // --- attention block (hn already holds in-norm) ---
        gemm_h128(p_hn, wq + (long)l * HH * HH, p_part, TT, HH, HH,
                  HH, HH, HH, 0, 0, 0, 1, 1, 4, (long)TT * HH);
        rope_rms_q_k<<<dim3(TT, NHEAD), 128>>>(q_ln + (long)l * HDIM, p_part);
        gemm_h64(p_hn, wk + (long)l * HH * 512, p_part, TT, 512, HH,
                 HH, 512, 512, 0, 0, 0, 1, 1, 4, (long)TT * 512);
        rope_rms_k_k<<<dim3(TT, KVHEAD), 128>>>(k_ln + (long)l * HDIM, p_part, nk_l);
        gemm_h64(p_hn, wv + (long)l * HH * 512, p_part, TT, 512, HH,
                 HH, 512, 512, 0, 0, 0, 1, 1, 4, (long)TT * 512);
        v_store_k<<<(TT * 512 + 255) / 256, 256>>>(p_part, nv_l);

        // scores[h] = Q_h [256,128] @ nk[kvh] [128,1280]  (batch 16)
        gemm_h128(p_q, nk_l, p_sc, TT, KVLEN, HDIM,
                  HH, KVLEN, KVLEN, 128, (long)HDIM * KVLEN, (long)TT * KVLEN,
                  4, NHEAD, 1, 0);
        softmax_k<<<dim3(TT, NHEAD), 256>>>(p_sc, flag);
        // attn_out[h] = P_h [256,1280] @ nv[kvh] [1280,128]  (batch 16)
        gemm_h64(p_sc, nv_l, p_ao, TT, HDIM, KVLEN,
                 KVLEN, HDIM, HH, (long)TT * KVLEN, (long)KVLEN * HDIM, 128,
                 4, NHEAD, 1, 0);
        // wo partials (split-K 4); then h += attn_out@wo, hn = postnorm(h)
        gemm_h128(p_ao, wo + (long)l * HH * HH, p_part, TT, HH, HH,
                  HH, HH, HH, 0, 0, 0, 1, 1, 4, (long)TT * HH);
        res_norm_k<<<TT, 256>>>(p_part, 4, (long)TT * HH, p_h,
                                post_ln + (long)l * HH, p_hn);

        // --- MLP block ---
        gemm_h128(p_hn, w_gate + (long)l * HH * FF, p_ga, TT, FF, HH,
                  HH, FF, FF, 0, 0, 0, 1, 1, 1, 0);
        gemm_h128(p_hn, w_up + (long)l * HH * FF, p_ga, TT, FF, HH,
                  HH, FF, FF, 0, 0, 0, 1, 1, 1, 0, 2, p_ga);
        gemm_h128(p_ga, w_down + (long)l * FF * HH, p_part, TT, HH, FF,
                  FF, HH, HH, 0, 0, 0, 1, 1, 8, (long)TT * HH);
        // h += mlp_out; hn = next norm (in_ln[l+1], or final_w after last layer)
        const float* nw = (l + 1 < LAYERS) ? (in_ln + (long)(l + 1) * HH) : final_w;
        res_norm_k<<<TT, 256>>>(p_part, 8, (long)TT * HH, p_h, nw, p_hn);
    }

    // lm_head on the final normed last-token row + argmax
    gemv_k<<<(VV + 255) / 256, 256>>>(lm_head, p_hn + (long)(TT - 1) * HH);
    argmax_k<<<1, 256>>>(out);
}

// round 14
// speedup vs baseline: 1.1814x; 1.1814x over previous
#include <cuda_runtime.h>
#include <cuda_fp16.h>
#include <math.h>
#include <stdint.h>

// ---------------------------------------------------------------------------
// Problem constants
// ---------------------------------------------------------------------------
constexpr int TT     = 256;    // ids_len
constexpr int HH     = 2048;   // hidden
constexpr int FF     = 8192;   // mlp intermediate
constexpr int VV     = 32000;  // vocab
constexpr int HDIM   = 128;
constexpr int NHEAD  = 16;
constexpr int KVHEAD = 4;
constexpr int HISTL  = 1024;
constexpr int KVLEN  = 1280;   // HIST + T
constexpr int LAYERS = 4;
constexpr float SCALE = 0.29730177875068026f; // 128^-0.25

constexpr long NK_LAYER = (long)KVHEAD * HDIM * KVLEN;   // 655360
constexpr long NV_OFF   = (long)LAYERS * NK_LAYER;       // 2621440
constexpr long TOK_OFF  = 2 * NV_OFF;                    // 5242880

// ---------------------------------------------------------------------------
// Static device scratch (no allocations allowed)
// ---------------------------------------------------------------------------
__device__ float g_h[TT * HH];
__device__ float g_hn[TT * HH];
__device__ float g_q[TT * HH];
__device__ float g_scores[NHEAD * TT * KVLEN];
__device__ float g_attnout[TT * HH];
__device__ float g_gate[TT * FF];
__device__ float g_part[4L * TT * FF];   // split-K partials (4 x 256x8192 max)
__device__ float g_cos[TT * 64];
__device__ float g_sin[TT * 64];
__device__ float g_logits[VV];
__device__ int   g_eq_dtype;   // 0=uint8 packed, 1=int32, 2=float32

// ---------------------------------------------------------------------------
// Dtype sniffer (embed_q may arrive as uint8 / int32 / float32)
// ---------------------------------------------------------------------------
__global__ void sniff_k(const int* __restrict__ eq_words) {
    __shared__ int not_int, not_flt;
    if (threadIdx.x == 0) { not_int = 0; not_flt = 0; }
    __syncthreads();
    for (int i = threadIdx.x; i < 4096; i += 256) {
        int x = eq_words[i];
        if (!(x >= 0 && x < 256)) not_int = 1;
        float f = __int_as_float(x);
        if (!(f >= 0.f && f < 256.f && f == rintf(f))) not_flt = 1;
    }
    __syncthreads();
    if (threadIdx.x == 0)
        g_eq_dtype = (!not_int) ? 1 : ((!not_flt) ? 2 : 0);
}

// ---------------------------------------------------------------------------
// FP16 tensor-core GEMM (legacy mma.sync path; sm_103 baseline ISA).
// C[M,N] = A[M,K] @ B[K,N]
//  - batch via blockIdx.z (A += z*sA, B += (z/bdiv)*sB, C += z*sC), OR
//  - split-K via blockIdx.z (slice K, write C + z*partElems, ldc=N)
//  - emode 2: C[i] = silu(peer[i]) * acc   (SwiGLU fusion; unused this round)
// ---------------------------------------------------------------------------
__device__ __forceinline__ void ldsm_x4(uint32_t& r0, uint32_t& r1,
                                        uint32_t& r2, uint32_t& r3, uint32_t a) {
    asm volatile("ldmatrix.sync.aligned.m8n8.x4.shared.b16 {%0,%1,%2,%3}, [%4];"
                 : "=r"(r0), "=r"(r1), "=r"(r2), "=r"(r3) : "r"(a));
}
__device__ __forceinline__ void ldsm_x4t(uint32_t& r0, uint32_t& r1,
                                         uint32_t& r2, uint32_t& r3, uint32_t a) {
    asm volatile("ldmatrix.sync.aligned.m8n8.x4.trans.shared.b16 {%0,%1,%2,%3}, [%4];"
                 : "=r"(r0), "=r"(r1), "=r"(r2), "=r"(r3) : "r"(a));
}
__device__ __forceinline__ void mma_f16(float* c, const uint32_t* a, const uint32_t* b) {
    asm volatile(
        "mma.sync.aligned.m16n8k16.row.col.f32.f16.f16.f32 "
        "{%0,%1,%2,%3}, {%4,%5,%6,%7}, {%8,%9}, {%0,%1,%2,%3};"
        : "+f"(c[0]), "+f"(c[1]), "+f"(c[2]), "+f"(c[3])
        : "r"(a[0]), "r"(a[1]), "r"(a[2]), "r"(a[3]), "r"(b[0]), "r"(b[1]));
}
__device__ __forceinline__ uint2 pack4(float4 v) {
    __half2 h0 = __floats2half2_rn(v.x, v.y);
    __half2 h1 = __floats2half2_rn(v.z, v.w);
    return make_uint2(*reinterpret_cast<uint32_t*>(&h0),
                      *reinterpret_cast<uint32_t*>(&h1));
}
__device__ __forceinline__ float silu_f(float g) { return g / (1.0f + expf(-g)); }

template <int BM, int BN, int WM, int WN, int NTH>
__global__ void __launch_bounds__(NTH)
gemm_f16(const float* __restrict__ A, const float* __restrict__ B,
         float* __restrict__ C,
         int M, int N, int K, int lda, int ldb, int ldc,
         long sA, long sB, long sC, int bdiv, int splitK, long partElems,
         int emode, const float* __restrict__ peer) {
    constexpr int BK   = 32;
    constexpr int WGN  = BN / WN;
    constexpr int MT   = WM / 16;
    constexpr int NT   = WN / 8;
    constexpr int AP   = BM * (BK / 4) / NTH;
    constexpr int BP   = BK * (BN / 4) / NTH;
    constexpr int ASTR = BK + 8;   // halves; 80B rows -> conflict-free ldmatrix
    constexpr int BSTR = BN + 8;

    __shared__ __half As[2][BM][ASTR];
    __shared__ __half Bs[2][BK][BSTR];

    const int z = blockIdx.z;
    int kbeg, kend;
    if (splitK > 1) {
        C += (long)z * partElems;
        const int Kb = K / splitK;
        kbeg = z * Kb;
        kend = kbeg + Kb;
    } else {
        A += (long)z * sA;
        B += (long)(z / bdiv) * sB;
        C += (long)z * sC;
        kbeg = 0;
        kend = K;
    }

    const int tid  = threadIdx.x;
    const int wid  = tid >> 5;
    const int lane = tid & 31;
    const int grp  = lane >> 2;
    const int t4   = lane & 3;
    const int wm0  = (wid / WGN) * WM;
    const int wn0  = (wid % WGN) * WN;
    const int bm   = blockIdx.y * BM;
    const int bn   = blockIdx.x * BN;
    const int lrow = lane & 15;
    const int lcol = (lane & 16) ? 8 : 0;

    float acc[MT][NT][4];
#pragma unroll
    for (int i = 0; i < MT; i++)
#pragma unroll
        for (int j = 0; j < NT; j++)
#pragma unroll
            for (int r = 0; r < 4; r++) acc[i][j][r] = 0.f;

    uint2 ra[AP], rb[BP];
    const int niter = (kend - kbeg) / BK;

    // ---- prologue: tile 0 -> regs -> stage 0 ----
#pragma unroll
    for (int p = 0; p < AP; p++) {
        int f = p * NTH + tid;
        ra[p] = pack4(*(const float4*)(A + (long)(bm + (f >> 3)) * lda + (kbeg + (f & 7) * 4)));
    }
#pragma unroll
    for (int p = 0; p < BP; p++) {
        int f = p * NTH + tid;
        rb[p] = pack4(*(const float4*)(B + (long)(kbeg + f / (BN / 4)) * ldb + (bn + (f % (BN / 4)) * 4)));
    }
#pragma unroll
    for (int p = 0; p < AP; p++) {
        int f = p * NTH + tid;
        *(uint2*)&As[0][f >> 3][(f & 7) * 4] = ra[p];
    }
#pragma unroll
    for (int p = 0; p < BP; p++) {
        int f = p * NTH + tid;
        *(uint2*)&Bs[0][f / (BN / 4)][(f % (BN / 4)) * 4] = rb[p];
    }

    int cur = 0;
    for (int it = 0; it < niter; it++) {
        __syncthreads();
        if (it + 1 < niter) {
            const int k0g = kbeg + (it + 1) * BK;
#pragma unroll
            for (int p = 0; p < AP; p++) {
                int f = p * NTH + tid;
                ra[p] = pack4(*(const float4*)(A + (long)(bm + (f >> 3)) * lda + (k0g + (f & 7) * 4)));
            }
#pragma unroll
            for (int p = 0; p < BP; p++) {
                int f = p * NTH + tid;
                rb[p] = pack4(*(const float4*)(B + (long)(k0g + f / (BN / 4)) * ldb + (bn + (f % (BN / 4)) * 4)));
            }
        }
        const uint32_t asB = (uint32_t)__cvta_generic_to_shared(&As[cur][0][0]);
        const uint32_t bsB = (uint32_t)__cvta_generic_to_shared(&Bs[cur][0][0]);
#pragma unroll
        for (int ks = 0; ks < 2; ks++) {
            uint32_t af[MT][4];
#pragma unroll
            for (int mt = 0; mt < MT; mt++) {
                uint32_t adr = asB + 2u * ((wm0 + mt * 16 + lrow) * ASTR + ks * 16 + lcol);
                ldsm_x4(af[mt][0], af[mt][1], af[mt][2], af[mt][3], adr);
            }
            uint32_t bf[NT][2];
#pragma unroll
            for (int np = 0; np < NT / 2; np++) {
                uint32_t bdr = bsB + 2u * ((ks * 16 + lrow) * BSTR + wn0 + np * 16 + lcol);
                ldsm_x4t(bf[2 * np][0], bf[2 * np][1],
                         bf[2 * np + 1][0], bf[2 * np + 1][1], bdr);
            }
#pragma unroll
            for (int mt = 0; mt < MT; mt++)
#pragma unroll
                for (int nt = 0; nt < NT; nt++) mma_f16(acc[mt][nt], af[mt], bf[nt]);
        }
        if (it + 1 < niter) {
            const int nxt = cur ^ 1;
#pragma unroll
            for (int p = 0; p < AP; p++) {
                int f = p * NTH + tid;
                *(uint2*)&As[nxt][f >> 3][(f & 7) * 4] = ra[p];
            }
#pragma unroll
            for (int p = 0; p < BP; p++) {
                int f = p * NTH + tid;
                *(uint2*)&Bs[nxt][f / (BN / 4)][(f % (BN / 4)) * 4] = rb[p];
            }
            cur = nxt;
        }
    }

    // ---- epilogue ----
#pragma unroll
    for (int mt = 0; mt < MT; mt++) {
        const int r0 = bm + wm0 + mt * 16 + grp;
#pragma unroll
        for (int nt = 0; nt < NT; nt++) {
            const int c0 = bn + wn0 + nt * 8 + t4 * 2;
            long i00 = (long)r0 * ldc + c0;
            long i10 = (long)(r0 + 8) * ldc + c0;
            if (emode == 2) {
                C[i00]     = silu_f(peer[i00])     * acc[mt][nt][0];
                C[i00 + 1] = silu_f(peer[i00 + 1]) * acc[mt][nt][1];
                C[i10]     = silu_f(peer[i10])     * acc[mt][nt][2];
                C[i10 + 1] = silu_f(peer[i10 + 1]) * acc[mt][nt][3];
            } else {
                C[i00]     = acc[mt][nt][0];
                C[i00 + 1] = acc[mt][nt][1];
                C[i10]     = acc[mt][nt][2];
                C[i10 + 1] = acc[mt][nt][3];
            }
        }
    }
}

// ---------------------------------------------------------------------------
// Fused SwiGLU split-K reduce: act = silu(g0+g1) * (u0+u1)
// gate partials at part[0..1], up partials at part[2..3], stride TT*FF.
// ---------------------------------------------------------------------------
__global__ void silu_reduce_k(const float* __restrict__ part, float* __restrict__ act) {
    long i = (long)blockIdx.x * blockDim.x + threadIdx.x;   // float4 index
    const long n4 = (long)TT * FF / 4;
    if (i >= n4) return;
    const float4* p = (const float4*)part;
    float4 g0 = p[i], g1 = p[i + n4];
    float4 u0 = p[i + 2 * n4], u1 = p[i + 3 * n4];
    float4 r;
    r.x = silu_f(g0.x + g1.x) * (u0.x + u1.x);
    r.y = silu_f(g0.y + g1.y) * (u0.y + u1.y);
    r.z = silu_f(g0.z + g1.z) * (u0.z + u1.z);
    r.w = silu_f(g0.w + g1.w) * (u0.w + u1.w);
    ((float4*)act)[i] = r;
}

// ---------------------------------------------------------------------------
// Fused: h += sum_s part[s]; hn = w * rms(h)
// ---------------------------------------------------------------------------
__global__ void res_norm_k(const float* __restrict__ part, int S, long stride,
                           float* __restrict__ h, const float* __restrict__ w,
                           float* __restrict__ hn) {
    int t = blockIdx.x;
    float4* hrow = (float4*)(h + (long)t * HH);
    __shared__ float red[256];
    float ssum = 0.f;
    for (int i = threadIdx.x; i < HH / 4; i += 256) {
        float4 a = hrow[i];
        for (int s = 0; s < S; s++) {
            float4 b = ((const float4*)(part + (long)s * stride + (long)t * HH))[i];
            a.x += b.x; a.y += b.y; a.z += b.z; a.w += b.w;
        }
        hrow[i] = a;
        ssum += a.x * a.x + a.y * a.y + a.z * a.z + a.w * a.w;
    }
    red[threadIdx.x] = ssum;
    __syncthreads();
    for (int o = 128; o > 0; o >>= 1) {
        if (threadIdx.x < o) red[threadIdx.x] += red[threadIdx.x + o];
        __syncthreads();
    }
    float inv = 1.0f / sqrtf(red[0] / (float)HH + 1e-6f);
    const float* hr = h + (long)t * HH;
    for (int d = threadIdx.x; d < HH; d += 256)
        hn[(long)t * HH + d] = w[d] * hr[d] * inv;
}

// ---------------------------------------------------------------------------
// Helper kernels
// ---------------------------------------------------------------------------
__global__ void rope_table_k() {
    int i = blockIdx.x * blockDim.x + threadIdx.x;
    if (i >= TT * 64) return;
    int t = i / 64, j = i % 64;
    float freq = powf(10000.0f, -((float)(2 * j)) / 128.0f);
    float ang = (float)(HISTL + t) * freq;
    g_cos[i] = __half2float(__float2half(cosf(ang)));
    g_sin[i] = __half2float(__float2half(sinf(ang)));
}

__global__ void embed_k(const int* __restrict__ ids, const void* __restrict__ eq,
                        const float* __restrict__ esc, const float* __restrict__ ezp) {
    int t = blockIdx.x;
    int id = ids[t];
    float sc = esc[id], zp = ezp[id];
    int dt = g_eq_dtype;
    long off = (long)id * HH;
    for (int d = threadIdx.x; d < HH; d += blockDim.x) {
        float qv;
        if (dt == 1)      qv = (float)((const int*)eq)[off + d];
        else if (dt == 2) qv = ((const float*)eq)[off + d];
        else              qv = (float)((const unsigned char*)eq)[off + d];
        g_h[t * HH + d] = qv * sc + zp;
    }
}

__global__ void rmsnorm_k(const float* __restrict__ x, const float* __restrict__ w,
                          float* __restrict__ y) {
    int t = blockIdx.x;
    const float* xr = x + (long)t * HH;
    __shared__ float red[256];
    float s = 0.f;
    for (int d = threadIdx.x; d < HH; d += 256) {
        float v = xr[d];
        s += v * v;
    }
    red[threadIdx.x] = s;
    __syncthreads();
    for (int o = 128; o > 0; o >>= 1) {
        if (threadIdx.x < o) red[threadIdx.x] += red[threadIdx.x + o];
        __syncthreads();
    }
    float inv = 1.0f / sqrtf(red[0] / (float)HH + 1e-6f);
    for (int d = threadIdx.x; d < HH; d += 256) y[(long)t * HH + d] = w[d] * xr[d] * inv;
}

// split-K reduce (S=4) + RoPE + per-head RMS for Q -> g_q.  grid (T,NH), 128 thr
__global__ void rope_rms_q_k(const float* __restrict__ w, const float* __restrict__ part) {
    int t = blockIdx.x, h = blockIdx.y, d = threadIdx.x;
    long idx = (long)t * HH + h * HDIM + d;
    float x = part[idx] + part[idx + (long)TT * HH] +
              part[idx + 2L * TT * HH] + part[idx + 3L * TT * HH];
    __shared__ float sq[128];
    __shared__ float red[128];
    sq[d] = x;
    __syncthreads();
    float other = (d < 64) ? -sq[d + 64] : sq[d - 64];
    float c = g_cos[t * 64 + (d & 63)];
    float sn = g_sin[t * 64 + (d & 63)];
    float r = sq[d] * c + other * sn;
    red[d] = r * r;
    __syncthreads();
    for (int o = 64; o > 0; o >>= 1) {
        if (d < o) red[d] += red[d + o];
        __syncthreads();
    }
    float inv = 1.0f / sqrtf(red[0] / 128.0f + 1e-6f);
    g_q[idx] = (w[d] * SCALE) * r * inv;
}

// split-K reduce (S=4) + RoPE + per-head RMS for K -> nk[l][kvh][d][KV] col HIST+t
__global__ void rope_rms_k_k(const float* __restrict__ w, const float* __restrict__ part,
                             float* __restrict__ nk_l) {
    int t = blockIdx.x, h = blockIdx.y, d = threadIdx.x;
    long idx = (long)t * 512 + h * HDIM + d;
    float x = part[idx] + part[idx + (long)TT * 512] +
              part[idx + 2L * TT * 512] + part[idx + 3L * TT * 512];
    __shared__ float sq[128];
    __shared__ float red[128];
    sq[d] = x;
    __syncthreads();
    float other = (d < 64) ? -sq[d + 64] : sq[d - 64];
    float c = g_cos[t * 64 + (d & 63)];
    float sn = g_sin[t * 64 + (d & 63)];
    float r = sq[d] * c + other * sn;
    red[d] = r * r;
    __syncthreads();
    for (int o = 64; o > 0; o >>= 1) {
        if (d < o) red[d] += red[d + o];
        __syncthreads();
    }
    float inv = 1.0f / sqrtf(red[0] / 128.0f + 1e-6f);
    nk_l[(long)h * HDIM * KVLEN + (long)d * KVLEN + (HISTL + t)] = (w[d] * SCALE) * r * inv;
}

// split-K reduce (S=4) + store new V rows into nv[l]: [kvh][KV][HD]
__global__ void v_store_k(const float* __restrict__ part, float* __restrict__ nv_l) {
    int i = blockIdx.x * blockDim.x + threadIdx.x;
    if (i >= TT * 512) return;
    float v = part[i] + part[i + TT * 512] + part[i + 2 * TT * 512] + part[i + 3 * TT * 512];
    int t = i >> 9, r = i & 511;
    int kvh = r >> 7, d = r & 127;
    nv_l[(long)kvh * KVLEN * HDIM + (long)(HISTL + t) * HDIM + d] = v;
}

__global__ void copy_kcache_k(const float* __restrict__ kc, float* __restrict__ out) {
    long i = (long)blockIdx.x * blockDim.x + threadIdx.x;
    const long total4 = (long)LAYERS * KVHEAD * HDIM * HISTL / 4;
    if (i >= total4) return;
    long row = i >> 8;
    long c4 = i & 255;
    long lk = row >> 7;
    long d = row & 127;
    float4 v = ((const float4*)kc)[i];
    long dst = lk * ((long)HDIM * KVLEN) + d * KVLEN + c4 * 4;
    *(float4*)(out + dst) = v;
}

__global__ void copy_vcache_k(const float* __restrict__ vc, float* __restrict__ outv) {
    long i = (long)blockIdx.x * blockDim.x + threadIdx.x;
    const long per4 = (long)HISTL * HDIM / 4;
    const long total4 = (long)LAYERS * KVHEAD * per4;
    if (i >= total4) return;
    long lk = i / per4;
    long rem = i - lk * per4;
    float4 v = ((const float4*)vc)[i];
    long dst = lk * ((long)KVLEN * HDIM) + rem * 4;
    *(float4*)(outv + dst) = v;
}

__global__ void softmax_k(float* __restrict__ s, const float* __restrict__ flagp) {
    int t = blockIdx.x, h = blockIdx.y;
    float flag = flagp[0];
    float* row = s + ((long)h * TT + t) * KVLEN;
    __shared__ float red[256];
    float m = -1e30f;
    for (int c = threadIdx.x; c < KVLEN; c += 256) {
        float v = row[c] + ((c <= t) ? 0.f : -128.f * flag);
        m = fmaxf(m, v);
    }
    red[threadIdx.x] = m;
    __syncthreads();
    for (int o = 128; o > 0; o >>= 1) {
        if (threadIdx.x < o) red[threadIdx.x] = fmaxf(red[threadIdx.x], red[threadIdx.x + o]);
        __syncthreads();
    }
    float mx = red[0];
    __syncthreads();
    float sum = 0.f;
    for (int c = threadIdx.x; c < KVLEN; c += 256) {
        float v = row[c] + ((c <= t) ? 0.f : -128.f * flag);
        float e = expf(v - mx);
        row[c] = e;
        sum += e;
    }
    red[threadIdx.x] = sum;
    __syncthreads();
    for (int o = 128; o > 0; o >>= 1) {
        if (threadIdx.x < o) red[threadIdx.x] += red[threadIdx.x + o];
        __syncthreads();
    }
    float inv = 1.0f / red[0];
    for (int c = threadIdx.x; c < KVLEN; c += 256) row[c] *= inv;
}

// lm_head GEMV over the final normed row (hl)
__global__ void gemv_k(const float* __restrict__ W, const float* __restrict__ hl) {
    __shared__ float sh[HH];
    for (int i = threadIdx.x; i < HH; i += blockDim.x) sh[i] = hl[i];
    __syncthreads();
    int v = blockIdx.x * blockDim.x + threadIdx.x;
    if (v >= VV) return;
    float acc = 0.f;
#pragma unroll 8
    for (int h = 0; h < HH; h++) acc += sh[h] * __ldg(&W[(long)h * VV + v]);
    g_logits[v] = acc;
}

__global__ void argmax_k(float* __restrict__ out) {
    __shared__ float bv[256];
    __shared__ int bi[256];
    float best = -1e30f;
    int bidx = 0;
    for (int v = threadIdx.x; v < VV; v += 256) {
        float x = g_logits[v];
        if (x > best) { best = x; bidx = v; }
    }
    bv[threadIdx.x] = best;
    bi[threadIdx.x] = bidx;
    __syncthreads();
    for (int o = 128; o > 0; o >>= 1) {
        if (threadIdx.x < o) {
            float a = bv[threadIdx.x], b = bv[threadIdx.x + o];
            int ia = bi[threadIdx.x], ib = bi[threadIdx.x + o];
            if (b > a || (b == a && ib < ia)) { bv[threadIdx.x] = b; bi[threadIdx.x] = ib; }
        }
        __syncthreads();
    }
    if (threadIdx.x == 0) {
        out[TOK_OFF] = (float)bi[0];
        out[TOK_OFF + 1] = (float)KVLEN;
    }
}

// ---------------------------------------------------------------------------
// Host-side launch helpers
// ---------------------------------------------------------------------------
static void gemm_h128(const float* A, const float* B, float* C, int M, int N, int K,
                      int lda, int ldb, int ldc, long sA, long sB, long sC,
                      int bdiv, int batch, int splitK, long partElems,
                      int emode = 0, const float* peer = nullptr) {
    dim3 g(N / 128, M / 128, splitK > 1 ? splitK : batch);
    gemm_f16<128, 128, 64, 32, 256><<<g, 256>>>(A, B, C, M, N, K, lda, ldb, ldc,
                                                sA, sB, sC, bdiv, splitK, partElems,
                                                emode, peer);
}
static void gemm_h64(const float* A, const float* B, float* C, int M, int N, int K,
                     int lda, int ldb, int ldc, long sA, long sB, long sC,
                     int bdiv, int batch, int splitK, long partElems) {
    dim3 g(N / 64, M / 64, splitK > 1 ? splitK : batch);
    gemm_f16<64, 64, 32, 32, 128><<<g, 128>>>(A, B, C, M, N, K, lda, ldb, ldc,
                                              sA, sB, sC, bdiv, splitK, partElems,
                                              0, nullptr);
}

extern "C" void kernel_launch(void* const* d_in, const int* in_sizes, int n_in,
                              void* d_out, int out_size) {
    const int* ids      = (const int*)d_in[0];
    const float* kcache = (const float*)d_in[1];
    const float* vcache = (const float*)d_in[2];
    const float* flag   = (const float*)d_in[3];

    int base = 6;
    for (int i = 4; i <= 6 && i < n_in; i++) {
        if (in_sizes[i] == VV * HH) { base = i; break; }
    }
    const void* eq          = d_in[base + 0];
    const float* esc        = (const float*)d_in[base + 1];
    const float* ezp        = (const float*)d_in[base + 2];
    const float* in_ln      = (const float*)d_in[base + 3];
    const float* wq         = (const float*)d_in[base + 4];
    const float* wk         = (const float*)d_in[base + 5];
    const float* wv         = (const float*)d_in[base + 6];
    const float* wo         = (const float*)d_in[base + 7];
    const float* q_ln       = (const float*)d_in[base + 8];
    const float* k_ln       = (const float*)d_in[base + 9];
    const float* post_ln    = (const float*)d_in[base + 10];
    const float* w_gate     = (const float*)d_in[base + 11];
    const float* w_up       = (const float*)d_in[base + 12];
    const float* w_down     = (const float*)d_in[base + 13];
    const float* final_w    = (const float*)d_in[base + 14];
    const float* lm_head    = (const float*)d_in[base + 15];
    float* out = (float*)d_out;

    float *p_h, *p_hn, *p_q, *p_sc, *p_ao, *p_ga, *p_part;
    cudaGetSymbolAddress((void**)&p_h, g_h);
    cudaGetSymbolAddress((void**)&p_hn, g_hn);
    cudaGetSymbolAddress((void**)&p_q, g_q);
    cudaGetSymbolAddress((void**)&p_sc, g_scores);
    cudaGetSymbolAddress((void**)&p_ao, g_attnout);
    cudaGetSymbolAddress((void**)&p_ga, g_gate);
    cudaGetSymbolAddress((void**)&p_part, g_part);

    // Prologue ordered so ncu's fixed "-s 5 -c 1" profiles the layer-0 wq GEMM.
    sniff_k<<<1, 256>>>((const int*)eq);                       // 0
    rope_table_k<<<64, 256>>>();                               // 1
    embed_k<<<256, 256>>>(ids, eq, esc, ezp);                  // 2
    rmsnorm_k<<<TT, 256>>>(p_h, in_ln, p_hn);                  // 3
    copy_kcache_k<<<2048, 256>>>(kcache, out);                 // 4
    gemm_h128(p_hn, wq, p_part, TT, HH, HH,                    // 5  <- profiled
              HH, HH, HH, 0, 0, 0, 1, 1, 4, (long)TT * HH);
    copy_vcache_k<<<2048, 256>>>(vcache, out + NV_OFF);        // 6

    for (int l = 0; l < LAYERS; l++) {
        float* nk_l = out + (long)l * NK_LAYER;
        float* nv_l = out + NV_OFF + (long)l * NK_LAYER;

        // --- attention block (hn holds current input norm) ---
        if (l > 0)
            gemm_h128(p_hn, wq + (long)l * HH * HH, p_part, TT, HH, HH,
                      HH, HH, HH, 0, 0, 0, 1, 1, 4, (long)TT * HH);
        rope_rms_q_k<<<dim3(TT, NHEAD), 128>>>(q_ln + (long)l * HDIM, p_part);
        gemm_h64(p_hn, wk + (long)l * HH * 512, p_part, TT, 512, HH,
                 HH, 512, 512, 0, 0, 0, 1, 1, 4, (long)TT * 512);
        rope_rms_k_k<<<dim3(TT, KVHEAD), 128>>>(k_ln + (long)l * HDIM, p_part, nk_l);
        gemm_h64(p_hn, wv + (long)l * HH * 512, p_part, TT, 512, HH,
                 HH, 512, 512, 0, 0, 0, 1, 1, 4, (long)TT * 512);
        v_store_k<<<(TT * 512 + 255) / 256, 256>>>(p_part, nv_l);

        // scores[h] = Q_h [256,128] @ nk[kvh] [128,1280]  (batch 16)
        gemm_h128(p_q, nk_l, p_sc, TT, KVLEN, HDIM,
                  HH, KVLEN, KVLEN, 128, (long)HDIM * KVLEN, (long)TT * KVLEN,
                  4, NHEAD, 1, 0);
        softmax_k<<<dim3(TT, NHEAD), 256>>>(p_sc, flag);
        // attn_out[h] = P_h [256,1280] @ nv[kvh] [1280,128]  (batch 16)
        gemm_h64(p_sc, nv_l, p_ao, TT, HDIM, KVLEN,
                 KVLEN, HDIM, HH, (long)TT * KVLEN, (long)KVLEN * HDIM, 128,
                 4, NHEAD, 1, 0);
        // wo partials (split-K 4); then h += attn_out@wo, hn = postnorm(h)
        gemm_h128(p_ao, wo + (long)l * HH * HH, p_part, TT, HH, HH,
                  HH, HH, HH, 0, 0, 0, 1, 1, 4, (long)TT * HH);
        res_norm_k<<<TT, 256>>>(p_part, 4, (long)TT * HH, p_h,
                                post_ln + (long)l * HH, p_hn);

        // --- MLP block: gate/up each split-K 2 (256 blocks), fused reduce ---
        gemm_h128(p_hn, w_gate + (long)l * HH * FF, p_part, TT, FF, HH,
                  HH, FF, FF, 0, 0, 0, 1, 1, 2, (long)TT * FF);
        gemm_h128(p_hn, w_up + (long)l * HH * FF, p_part + 2L * TT * FF,
                  TT, FF, HH, HH, FF, FF, 0, 0, 0, 1, 1, 2, (long)TT * FF);
        silu_reduce_k<<<(TT * FF / 4 + 255) / 256, 256>>>(p_part, p_ga);
        // h += act @ w_down  (split-K 8 -> 256 blocks)
        gemm_h128(p_ga, w_down + (long)l * FF * HH, p_part, TT, HH, FF,
                  FF, HH, HH, 0, 0, 0, 1, 1, 8, (long)TT * HH);
        const float* nw = (l + 1 < LAYERS) ? (in_ln + (long)(l + 1) * HH) : final_w;
        res_norm_k<<<TT, 256>>>(p_part, 8, (long)TT * HH, p_h, nw, p_hn);
    }

    gemv_k<<<(VV + 255) / 256, 256>>>(lm_head, p_hn + (long)(TT - 1) * HH);
    argmax_k<<<1, 256>>>(out);
}